// round 13
// baseline (speedup 1.0000x reference)
#include <cuda_runtime.h>
#include <cuda_fp16.h>
#include <cstdint>

#define B_DIM 8
#define T_DIM 2048
#define D_DIM 2048
#define M_DIM (B_DIM * T_DIM)   // 16384

// ---------------- device-global scratch (static, allowed) -------------------
__device__ __align__(256) __half g_Ph[(size_t)M_DIM * D_DIM];  // (x@Wp^T+bp)/6, fp16
__device__ __align__(256) __half g_A [(size_t)M_DIM * D_DIM];  // fp16(x)
__device__ __align__(256) __half g_B [(size_t)D_DIM * D_DIM];  // fp16(Wp)

// ---------------- helpers ----------------------------------------------------
__device__ __forceinline__ uint32_t smem_u32(const void* p) {
    uint32_t a;
    asm("{ .reg .u64 t; cvta.to.shared.u64 t, %1; cvt.u32.u64 %0, t; }" : "=r"(a) : "l"(p));
    return a;
}
__device__ __forceinline__ void cp16(uint32_t sdst, const void* gsrc) {
    asm volatile("cp.async.cg.shared.global [%0], [%1], 16;" :: "r"(sdst), "l"(gsrc));
}
__device__ __forceinline__ uint32_t sw128(uint32_t o) { return o ^ ((o >> 3) & 0x70); }

__device__ __forceinline__ void ldmatrix_x4(uint32_t* f, uint32_t addr) {
    asm volatile("ldmatrix.sync.aligned.m8n8.x4.shared.b16 {%0,%1,%2,%3}, [%4];"
                 : "=r"(f[0]), "=r"(f[1]), "=r"(f[2]), "=r"(f[3]) : "r"(addr));
}
__device__ __forceinline__ void mma16816(float* c, const uint32_t* a,
                                         uint32_t b0, uint32_t b1) {
    asm volatile(
        "mma.sync.aligned.m16n8k16.row.col.f32.f16.f16.f32 "
        "{%0,%1,%2,%3}, {%4,%5,%6,%7}, {%8,%9}, {%0,%1,%2,%3};"
        : "+f"(c[0]), "+f"(c[1]), "+f"(c[2]), "+f"(c[3])
        : "r"(a[0]), "r"(a[1]), "r"(a[2]), "r"(a[3]), "r"(b0), "r"(b1));
}

// ---------------- fp32 -> fp16 convert (x and Wp, 8 elems/thread) ------------
__global__ __launch_bounds__(256) void cvt_fp16_kernel(
    const float4* __restrict__ xs, const float4* __restrict__ ws,
    uint4* __restrict__ da, uint4* __restrict__ db, int nx8, int ntot8) {
    int i = blockIdx.x * 256 + threadIdx.x;
    if (i >= ntot8) return;
    const bool isx = (i < nx8);
    const float4* src = isx ? (xs + 2 * (size_t)i) : (ws + 2 * (size_t)(i - nx8));
    const float4 v0 = src[0];
    const float4 v1 = src[1];
    __half2 h0 = __floats2half2_rn(v0.x, v0.y);
    __half2 h1 = __floats2half2_rn(v0.z, v0.w);
    __half2 h2 = __floats2half2_rn(v1.x, v1.y);
    __half2 h3 = __floats2half2_rn(v1.z, v1.w);
    uint4 o = make_uint4(*reinterpret_cast<const uint32_t*>(&h0),
                         *reinterpret_cast<const uint32_t*>(&h1),
                         *reinterpret_cast<const uint32_t*>(&h2),
                         *reinterpret_cast<const uint32_t*>(&h3));
    if (isx) da[i] = o; else db[i - nx8] = o;
}

// ---------------- HMMA GEMM: g_Ph = fp16((A @ B^T + bp) / 6) -----------------
// CTA 128x128, 128 threads (4 warps 2x2 => 64x64 warp tile), BK=64,
// 3-stage cp.async pipeline (96KB smem -> 2 CTAs/SM), explicit
// double-buffered ldmatrix fragments (R8/R12 proven schedule, untouched).
namespace hg {
constexpr int BM = 128, BN = 128, BK = 64, STAGES = 3;
constexpr int NKT = D_DIM / BK;                 // 32
constexpr int TILE_A = BM * 128;                // 16 KB
constexpr int TILE_B = BN * 128;                // 16 KB
constexpr int SMEM_BYTES = STAGES * (TILE_A + TILE_B) + 1024;  // 99328
}

__global__ __launch_bounds__(128, 2) void gemm_hmma_kernel(const float* __restrict__ bias) {
    using namespace hg;
    extern __shared__ char smem_raw[];
    const uint32_t sbase = (smem_u32(smem_raw) + 1023u) & ~1023u;
    const uint32_t bbase = sbase + STAGES * TILE_A;

    const int tid  = threadIdx.x;
    const int wid  = tid >> 5;
    const int lane = tid & 31;
    const int brow = blockIdx.y * BM;
    const int bcol = blockIdx.x * BN;
    const int wm = wid & 1;
    const int wn = wid >> 1;

    const __half* Ag = g_A + (size_t)brow * D_DIM;
    const __half* Bg = g_B + (size_t)bcol * D_DIM;

    const int lrow = tid >> 3;   // 0..15
    const int lseg = tid & 7;

    auto load_stage = [&](int s, int k0) {
        const uint32_t a_s = sbase + s * TILE_A;
        const uint32_t b_s = bbase + s * TILE_B;
#pragma unroll
        for (int p = 0; p < 8; p++) {
            const int row = lrow + p * 16;
            const uint32_t off = sw128((uint32_t)(row * 128 + lseg * 16));
            const size_t gofs = (size_t)row * D_DIM + k0 + lseg * 8;
            cp16(a_s + off, Ag + gofs);
            cp16(b_s + off, Bg + gofs);
        }
    };

    const int a_r_base = wm * 64 + (lane & 15);
    const int ab_cb    = ((lane >> 4) << 4);
    const int b_r_base = wn * 64 + (lane & 7) + ((lane >> 3) & 1) * 8;

    auto load_frags = [&](uint32_t (&af)[4][4], uint32_t (&bf)[4][4],
                          int s, int kb) {
        const uint32_t a_s = sbase + s * TILE_A;
        const uint32_t b_s = bbase + s * TILE_B;
#pragma unroll
        for (int i = 0; i < 4; i++)
            ldmatrix_x4(af[i], a_s + sw128((uint32_t)((a_r_base + i * 16) * 128 + kb + ab_cb)));
#pragma unroll
        for (int j = 0; j < 4; j++)
            ldmatrix_x4(bf[j], b_s + sw128((uint32_t)((b_r_base + j * 16) * 128 + kb + ab_cb)));
    };

    float acc[4][8][4];
#pragma unroll
    for (int i = 0; i < 4; i++)
#pragma unroll
        for (int j = 0; j < 8; j++)
#pragma unroll
            for (int e = 0; e < 4; e++) acc[i][j][e] = 0.0f;

    auto mma_all = [&](uint32_t (&af)[4][4], uint32_t (&bf)[4][4]) {
#pragma unroll
        for (int i = 0; i < 4; i++)
#pragma unroll
            for (int j = 0; j < 4; j++) {
                mma16816(acc[i][2 * j],     af[i], bf[j][0], bf[j][2]);
                mma16816(acc[i][2 * j + 1], af[i], bf[j][1], bf[j][3]);
            }
    };

    // prologue: stages 0 and 1 in flight
    load_stage(0, 0);
    asm volatile("cp.async.commit_group;" ::: "memory");
    load_stage(1, BK);
    asm volatile("cp.async.commit_group;" ::: "memory");
    asm volatile("cp.async.wait_group 1;" ::: "memory");   // stage 0 ready
    __syncthreads();

    uint32_t af[2][4][4], bf[2][4][4];
    load_frags(af[0], bf[0], 0, 0);

#pragma unroll 1
    for (int kt = 0; kt < NKT; kt++) {
        const int s = kt % STAGES;
        // prefetch stage kt+2 (empty commit keeps group accounting uniform)
        const int pf = kt + 2;
        if (pf < NKT) load_stage(pf % STAGES, pf * BK);
        asm volatile("cp.async.commit_group;" ::: "memory");

#pragma unroll
        for (int kk = 0; kk < BK / 16; kk++) {
            const int cur = kk & 1, nxt = cur ^ 1;
            if (kk < 3) {
                load_frags(af[nxt], bf[nxt], s, (kk + 1) * 32);
            } else if (kt + 1 < NKT) {
                asm volatile("cp.async.wait_group 1;" ::: "memory");  // stage kt+1 ready
                load_frags(af[nxt], bf[nxt], (kt + 1) % STAGES, 0);
            }
            mma_all(af[cur], bf[cur]);
        }
        __syncthreads();   // all warps done reading stage kt before it is overwritten
    }

    // epilogue: fp16 store of (acc + bias) / 6
    const float inv6 = 1.0f / 6.0f;
    const int prow0 = brow + wm * 64 + (lane >> 2);
    const int pcol0 = bcol + wn * 64 + (lane & 3) * 2;
#pragma unroll
    for (int i = 0; i < 4; i++) {
        const size_t r0 = (size_t)(prow0 + i * 16);
#pragma unroll
        for (int j = 0; j < 8; j++) {
            const int c = pcol0 + j * 8;
            const float b0 = bias[c], b1 = bias[c + 1];
            __half2 lo = __floats2half2_rn((acc[i][j][0] + b0) * inv6,
                                           (acc[i][j][1] + b1) * inv6);
            __half2 hi = __floats2half2_rn((acc[i][j][2] + b0) * inv6,
                                           (acc[i][j][3] + b1) * inv6);
            *reinterpret_cast<__half2*>(&g_Ph[r0 * D_DIM + c])       = lo;
            *reinterpret_cast<__half2*>(&g_Ph[(r0 + 8) * D_DIM + c]) = hi;
        }
    }
}

// ---------------- fused chained LayerNorm (float4, 512 threads/row) ----------
__device__ __forceinline__ float2 block_sum2_512(float a, float b) {
    __shared__ float sm[32];
    const int lane = threadIdx.x & 31;
    const int wid  = threadIdx.x >> 5;   // 0..15
#pragma unroll
    for (int o = 16; o > 0; o >>= 1) {
        a += __shfl_xor_sync(0xffffffffu, a, o);
        b += __shfl_xor_sync(0xffffffffu, b, o);
    }
    __syncthreads();
    if (lane == 0) { sm[wid] = a; sm[16 + wid] = b; }
    __syncthreads();
    float sa = 0.0f, sb = 0.0f;
#pragma unroll
    for (int i = 0; i < 16; i++) { sa += sm[i]; sb += sm[16 + i]; }
    return make_float2(sa, sb);
}

__global__ __launch_bounds__(512) void ln_fuse_kernel(
    const float* __restrict__ x, const float* __restrict__ gamma,
    const float* __restrict__ beta, float* __restrict__ out) {
    const int r   = blockIdx.x;
    const int t   = r & (T_DIM - 1);
    const int q   = threadIdx.x;         // one float4 chunk per thread
    const float invD = 1.0f / (float)D_DIM;
    constexpr int C4 = D_DIM / 4;        // 512 chunks per row

    const float4* xr = (const float4*)x + (size_t)r * C4;
    const int p1row  = (t == 0) ? (r + 1) : (r - 1);
    const uint2* p1  = (const uint2*)g_Ph + (size_t)p1row * C4;  // 4 halves / chunk
    const float4* g4 = (const float4*)gamma;
    const float4* b4 = (const float4*)beta;

    float4 v;
    {
        const float4 xv = xr[q];
        const uint2  pu = p1[q];
        const float2 pl = __half22float2(*reinterpret_cast<const __half2*>(&pu.x));
        const float2 ph = __half22float2(*reinterpret_cast<const __half2*>(&pu.y));
        v.x = xv.x + pl.x; v.y = xv.y + pl.y;
        v.z = xv.z + ph.x; v.w = xv.w + ph.y;
    }
    float s  = v.x + v.y + v.z + v.w;
    float sq = v.x * v.x + v.y * v.y + v.z * v.z + v.w * v.w;
    float2 red = block_sum2_512(s, sq);
    float mean = red.x * invD;
    float var  = red.y * invD - mean * mean;
    float rstd = rsqrtf(var + 1e-5f);

    const float4 gg = g4[q], bb = b4[q];

    if (t >= 1 && t <= T_DIM - 2) {
        const uint2* p2 = (const uint2*)g_Ph + (size_t)(r + 1) * C4;
        const uint2  pu = p2[q];
        const float2 pl = __half22float2(*reinterpret_cast<const __half2*>(&pu.x));
        const float2 ph = __half22float2(*reinterpret_cast<const __half2*>(&pu.y));
        v.x = (v.x - mean) * rstd * gg.x + bb.x + pl.x;
        v.y = (v.y - mean) * rstd * gg.y + bb.y + pl.y;
        v.z = (v.z - mean) * rstd * gg.z + bb.z + ph.x;
        v.w = (v.w - mean) * rstd * gg.w + bb.w + ph.y;
        s  = v.x + v.y + v.z + v.w;
        sq = v.x * v.x + v.y * v.y + v.z * v.z + v.w * v.w;
        red  = block_sum2_512(s, sq);
        mean = red.x * invD;
        var  = red.y * invD - mean * mean;
        rstd = rsqrtf(var + 1e-5f);
    }

    float4 o;
    o.x = (v.x - mean) * rstd * gg.x + bb.x;
    o.y = (v.y - mean) * rstd * gg.y + bb.y;
    o.z = (v.z - mean) * rstd * gg.z + bb.z;
    o.w = (v.w - mean) * rstd * gg.w + bb.w;
    ((float4*)out)[(size_t)r * C4 + q] = o;
}

// ---------------- launch ------------------------------------------------------
extern "C" void kernel_launch(void* const* d_in, const int* in_sizes, int n_in,
                              void* d_out, int out_size) {
    const float* x     = (const float*)d_in[0];
    const float* Wp    = (const float*)d_in[5];
    const float* bp    = (const float*)d_in[6];
    const float* gamma = (const float*)d_in[7];
    const float* beta  = (const float*)d_in[8];
    float* out = (float*)d_out;

    static bool attr_set = false;
    if (!attr_set) {
        cudaFuncSetAttribute(gemm_hmma_kernel,
                             cudaFuncAttributeMaxDynamicSharedMemorySize, hg::SMEM_BYTES);
        attr_set = true;
    }

    __half* gA; cudaGetSymbolAddress((void**)&gA, g_A);
    __half* gB; cudaGetSymbolAddress((void**)&gB, g_B);

    const int nx8  = M_DIM * D_DIM / 8;
    const int nw8  = D_DIM * D_DIM / 8;
    const int ntot = nx8 + nw8;
    cvt_fp16_kernel<<<(ntot + 255) / 256, 256>>>(
        (const float4*)x, (const float4*)Wp, (uint4*)gA, (uint4*)gB, nx8, ntot);

    dim3 ggrid(D_DIM / hg::BN, M_DIM / hg::BM);   // (16, 128)
    gemm_hmma_kernel<<<ggrid, 128, hg::SMEM_BYTES>>>(bp);

    ln_fuse_kernel<<<M_DIM, 512>>>(x, gamma, beta, out);
}

// round 14
// speedup vs baseline: 1.0744x; 1.0744x over previous
#include <cuda_runtime.h>
#include <cuda_fp16.h>
#include <cstdint>

#define B_DIM 8
#define T_DIM 2048
#define D_DIM 2048
#define M_DIM (B_DIM * T_DIM)   // 16384

// ---------------- device-global scratch (static, allowed) -------------------
__device__ __align__(256) __half g_Ph[(size_t)M_DIM * D_DIM];  // (x@Wp^T+bp)/6, fp16
__device__ __align__(256) __half g_A [(size_t)M_DIM * D_DIM];  // fp16(x)
__device__ __align__(256) __half g_B [(size_t)D_DIM * D_DIM];  // fp16(Wp)

// ---------------- helpers ----------------------------------------------------
__device__ __forceinline__ uint32_t smem_u32(const void* p) {
    uint32_t a;
    asm("{ .reg .u64 t; cvta.to.shared.u64 t, %1; cvt.u32.u64 %0, t; }" : "=r"(a) : "l"(p));
    return a;
}
__device__ __forceinline__ void cp16(uint32_t sdst, const void* gsrc) {
    asm volatile("cp.async.cg.shared.global [%0], [%1], 16;" :: "r"(sdst), "l"(gsrc));
}
__device__ __forceinline__ uint32_t sw128(uint32_t o) { return o ^ ((o >> 3) & 0x70); }

__device__ __forceinline__ void ldmatrix_x4(uint32_t* f, uint32_t addr) {
    asm volatile("ldmatrix.sync.aligned.m8n8.x4.shared.b16 {%0,%1,%2,%3}, [%4];"
                 : "=r"(f[0]), "=r"(f[1]), "=r"(f[2]), "=r"(f[3]) : "r"(addr));
}
__device__ __forceinline__ void mma16816(float* c, const uint32_t* a,
                                         uint32_t b0, uint32_t b1) {
    asm volatile(
        "mma.sync.aligned.m16n8k16.row.col.f32.f16.f16.f32 "
        "{%0,%1,%2,%3}, {%4,%5,%6,%7}, {%8,%9}, {%0,%1,%2,%3};"
        : "+f"(c[0]), "+f"(c[1]), "+f"(c[2]), "+f"(c[3])
        : "r"(a[0]), "r"(a[1]), "r"(a[2]), "r"(a[3]), "r"(b0), "r"(b1));
}

// ---------------- fp32 -> fp16 convert (x and Wp, 8 elems/thread) ------------
__global__ __launch_bounds__(256) void cvt_fp16_kernel(
    const float4* __restrict__ xs, const float4* __restrict__ ws,
    uint4* __restrict__ da, uint4* __restrict__ db, int nx8, int ntot8) {
    int i = blockIdx.x * 256 + threadIdx.x;
    if (i >= ntot8) return;
    const bool isx = (i < nx8);
    const float4* src = isx ? (xs + 2 * (size_t)i) : (ws + 2 * (size_t)(i - nx8));
    const float4 v0 = src[0];
    const float4 v1 = src[1];
    __half2 h0 = __floats2half2_rn(v0.x, v0.y);
    __half2 h1 = __floats2half2_rn(v0.z, v0.w);
    __half2 h2 = __floats2half2_rn(v1.x, v1.y);
    __half2 h3 = __floats2half2_rn(v1.z, v1.w);
    uint4 o = make_uint4(*reinterpret_cast<const uint32_t*>(&h0),
                         *reinterpret_cast<const uint32_t*>(&h1),
                         *reinterpret_cast<const uint32_t*>(&h2),
                         *reinterpret_cast<const uint32_t*>(&h3));
    if (isx) da[i] = o; else db[i - nx8] = o;
}

// ---------------- HMMA GEMM: g_Ph = fp16((A @ B^T + bp) / 6) -----------------
// CTA 128x128, 128 threads (4 warps 2x2 => 64x64 warp tile), BK=64,
// 3-stage cp.async pipeline (96KB smem -> 2 CTAs/SM), double-buffered
// ldmatrix fragments. kt loop unrolled in groups of 3 so every stage index
// (and hence every smem base) is a compile-time constant.
namespace hg {
constexpr int BM = 128, BN = 128, BK = 64, STAGES = 3;
constexpr int NKT = D_DIM / BK;                 // 32
constexpr int TILE_A = BM * 128;                // 16 KB
constexpr int TILE_B = BN * 128;                // 16 KB
constexpr int SMEM_BYTES = STAGES * (TILE_A + TILE_B) + 1024;  // 99328
}

__global__ __launch_bounds__(128, 2) void gemm_hmma_kernel(const float* __restrict__ bias) {
    using namespace hg;
    extern __shared__ char smem_raw[];
    const uint32_t sbase = (smem_u32(smem_raw) + 1023u) & ~1023u;
    const uint32_t bbase = sbase + STAGES * TILE_A;

    const int tid  = threadIdx.x;
    const int wid  = tid >> 5;
    const int lane = tid & 31;
    const int brow = blockIdx.y * BM;
    const int bcol = blockIdx.x * BN;
    const int wm = wid & 1;
    const int wn = wid >> 1;

    const __half* Ag = g_A + (size_t)brow * D_DIM;
    const __half* Bg = g_B + (size_t)bcol * D_DIM;

    const int lrow = tid >> 3;   // 0..15
    const int lseg = tid & 7;

    auto load_stage = [&](int s, int k0) {
        const uint32_t a_s = sbase + s * TILE_A;
        const uint32_t b_s = bbase + s * TILE_B;
#pragma unroll
        for (int p = 0; p < 8; p++) {
            const int row = lrow + p * 16;
            const uint32_t off = sw128((uint32_t)(row * 128 + lseg * 16));
            const size_t gofs = (size_t)row * D_DIM + k0 + lseg * 8;
            cp16(a_s + off, Ag + gofs);
            cp16(b_s + off, Bg + gofs);
        }
    };

    const int a_r_base = wm * 64 + (lane & 15);
    const int ab_cb    = ((lane >> 4) << 4);
    const int b_r_base = wn * 64 + (lane & 7) + ((lane >> 3) & 1) * 8;

    auto load_frags = [&](uint32_t (&af)[4][4], uint32_t (&bf)[4][4],
                          int s, int kb) {
        const uint32_t a_s = sbase + s * TILE_A;
        const uint32_t b_s = bbase + s * TILE_B;
#pragma unroll
        for (int i = 0; i < 4; i++)
            ldmatrix_x4(af[i], a_s + sw128((uint32_t)((a_r_base + i * 16) * 128 + kb + ab_cb)));
#pragma unroll
        for (int j = 0; j < 4; j++)
            ldmatrix_x4(bf[j], b_s + sw128((uint32_t)((b_r_base + j * 16) * 128 + kb + ab_cb)));
    };

    float acc[4][8][4];
#pragma unroll
    for (int i = 0; i < 4; i++)
#pragma unroll
        for (int j = 0; j < 8; j++)
#pragma unroll
            for (int e = 0; e < 4; e++) acc[i][j][e] = 0.0f;

    auto mma_all = [&](uint32_t (&af)[4][4], uint32_t (&bf)[4][4]) {
#pragma unroll
        for (int i = 0; i < 4; i++)
#pragma unroll
            for (int j = 0; j < 4; j++) {
                mma16816(acc[i][2 * j],     af[i], bf[j][0], bf[j][2]);
                mma16816(acc[i][2 * j + 1], af[i], bf[j][1], bf[j][3]);
            }
    };

    // prologue: stages 0 and 1 in flight
    load_stage(0, 0);
    asm volatile("cp.async.commit_group;" ::: "memory");
    load_stage(1, BK);
    asm volatile("cp.async.commit_group;" ::: "memory");
    asm volatile("cp.async.wait_group 1;" ::: "memory");   // stage 0 ready
    __syncthreads();

    uint32_t af[2][4][4], bf[2][4][4];
    load_frags(af[0], bf[0], 0, 0);

    // One kt iteration with stage S (compile-time), prefetch target SLD=(S+2)%3,
    // next-frag stage SNXT=(S+1)%3. Identical schedule to the R12 loop body.
#define KT_BODY(S, SLD, SNXT, KT)                                             \
    {                                                                         \
        const int pf = (KT) + 2;                                              \
        if (pf < NKT) load_stage((SLD), pf * BK);                             \
        asm volatile("cp.async.commit_group;" ::: "memory");                  \
        _Pragma("unroll")                                                     \
        for (int kk = 0; kk < BK / 16; kk++) {                                \
            const int cur = kk & 1, nxt = cur ^ 1;                            \
            if (kk < 3) {                                                     \
                load_frags(af[nxt], bf[nxt], (S), (kk + 1) * 32);             \
            } else if ((KT) + 1 < NKT) {                                      \
                asm volatile("cp.async.wait_group 1;" ::: "memory");          \
                load_frags(af[nxt], bf[nxt], (SNXT), 0);                      \
            }                                                                 \
            mma_all(af[cur], bf[cur]);                                        \
        }                                                                     \
        __syncthreads();                                                      \
    }

#pragma unroll 1
    for (int ktg = 0; ktg < NKT - 2; ktg += 3) {   // 0,3,...,27 (10 groups)
        KT_BODY(0, 2, 1, ktg);
        KT_BODY(1, 0, 2, ktg + 1);
        KT_BODY(2, 1, 0, ktg + 2);
    }
    KT_BODY(0, 2, 1, NKT - 2);   // kt = 30, stage 0
    KT_BODY(1, 0, 2, NKT - 1);   // kt = 31, stage 1
#undef KT_BODY

    // epilogue: fp16 store of (acc + bias) / 6
    const float inv6 = 1.0f / 6.0f;
    const int prow0 = brow + wm * 64 + (lane >> 2);
    const int pcol0 = bcol + wn * 64 + (lane & 3) * 2;
#pragma unroll
    for (int i = 0; i < 4; i++) {
        const size_t r0 = (size_t)(prow0 + i * 16);
#pragma unroll
        for (int j = 0; j < 8; j++) {
            const int c = pcol0 + j * 8;
            const float b0 = bias[c], b1 = bias[c + 1];
            __half2 lo = __floats2half2_rn((acc[i][j][0] + b0) * inv6,
                                           (acc[i][j][1] + b1) * inv6);
            __half2 hi = __floats2half2_rn((acc[i][j][2] + b0) * inv6,
                                           (acc[i][j][3] + b1) * inv6);
            *reinterpret_cast<__half2*>(&g_Ph[r0 * D_DIM + c])       = lo;
            *reinterpret_cast<__half2*>(&g_Ph[(r0 + 8) * D_DIM + c]) = hi;
        }
    }
}

// ---------------- fused chained LayerNorm (R12 proven: 256 thr, float2) ------
__device__ __forceinline__ float2 block_sum2(float a, float b) {
    __shared__ float sm[16];
    const int lane = threadIdx.x & 31;
    const int wid  = threadIdx.x >> 5;
#pragma unroll
    for (int o = 16; o > 0; o >>= 1) {
        a += __shfl_xor_sync(0xffffffffu, a, o);
        b += __shfl_xor_sync(0xffffffffu, b, o);
    }
    __syncthreads();
    if (lane == 0) { sm[wid] = a; sm[8 + wid] = b; }
    __syncthreads();
    float sa = 0.0f, sb = 0.0f;
#pragma unroll
    for (int i = 0; i < 8; i++) { sa += sm[i]; sb += sm[8 + i]; }
    return make_float2(sa, sb);
}

__global__ __launch_bounds__(256) void ln_fuse_kernel(
    const float* __restrict__ x, const float* __restrict__ gamma,
    const float* __restrict__ beta, float* __restrict__ out) {
    const int r   = blockIdx.x;
    const int t   = r & (T_DIM - 1);
    const int tid = threadIdx.x;
    const float invD = 1.0f / (float)D_DIM;
    constexpr int DP = D_DIM / 2;

    const float2*  xr = (const float2*)x + (size_t)r * DP;
    const int p1row   = (t == 0) ? (r + 1) : (r - 1);
    const __half2* p1 = (const __half2*)g_Ph + (size_t)p1row * DP;
    const float2*  g2 = (const float2*)gamma;
    const float2*  b2 = (const float2*)beta;

    float2 v[4];
    float s = 0.0f, sq = 0.0f;
#pragma unroll
    for (int i = 0; i < 4; i++) {
        const int q = i * 256 + tid;
        const float2 xv = xr[q];
        const float2 pv = __half22float2(p1[q]);
        const float a = xv.x + pv.x, b = xv.y + pv.y;
        v[i] = make_float2(a, b);
        s += a + b; sq += a * a + b * b;
    }
    float2 red = block_sum2(s, sq);
    float mean = red.x * invD;
    float var  = red.y * invD - mean * mean;
    float rstd = rsqrtf(var + 1e-5f);

    if (t >= 1 && t <= T_DIM - 2) {
        const __half2* p2 = (const __half2*)g_Ph + (size_t)(r + 1) * DP;
        s = 0.0f; sq = 0.0f;
#pragma unroll
        for (int i = 0; i < 4; i++) {
            const int q = i * 256 + tid;
            const float2 gg = g2[q], bb = b2[q];
            const float2 pv = __half22float2(p2[q]);
            const float a = (v[i].x - mean) * rstd * gg.x + bb.x + pv.x;
            const float b = (v[i].y - mean) * rstd * gg.y + bb.y + pv.y;
            v[i] = make_float2(a, b);
            s += a + b; sq += a * a + b * b;
        }
        red  = block_sum2(s, sq);
        mean = red.x * invD;
        var  = red.y * invD - mean * mean;
        rstd = rsqrtf(var + 1e-5f);
    }

    float2* orow = (float2*)out + (size_t)r * DP;
#pragma unroll
    for (int i = 0; i < 4; i++) {
        const int q = i * 256 + tid;
        const float2 gg = g2[q], bb = b2[q];
        orow[q] = make_float2((v[i].x - mean) * rstd * gg.x + bb.x,
                              (v[i].y - mean) * rstd * gg.y + bb.y);
    }
}

// ---------------- launch ------------------------------------------------------
extern "C" void kernel_launch(void* const* d_in, const int* in_sizes, int n_in,
                              void* d_out, int out_size) {
    const float* x     = (const float*)d_in[0];
    const float* Wp    = (const float*)d_in[5];
    const float* bp    = (const float*)d_in[6];
    const float* gamma = (const float*)d_in[7];
    const float* beta  = (const float*)d_in[8];
    float* out = (float*)d_out;

    static bool attr_set = false;
    if (!attr_set) {
        cudaFuncSetAttribute(gemm_hmma_kernel,
                             cudaFuncAttributeMaxDynamicSharedMemorySize, hg::SMEM_BYTES);
        attr_set = true;
    }

    __half* gA; cudaGetSymbolAddress((void**)&gA, g_A);
    __half* gB; cudaGetSymbolAddress((void**)&gB, g_B);

    const int nx8  = M_DIM * D_DIM / 8;
    const int nw8  = D_DIM * D_DIM / 8;
    const int ntot = nx8 + nw8;
    cvt_fp16_kernel<<<(ntot + 255) / 256, 256>>>(
        (const float4*)x, (const float4*)Wp, (uint4*)gA, (uint4*)gB, nx8, ntot);

    dim3 ggrid(D_DIM / hg::BN, M_DIM / hg::BM);   // (16, 128)
    gemm_hmma_kernel<<<ggrid, 128, hg::SMEM_BYTES>>>(bp);

    ln_fuse_kernel<<<M_DIM, 256>>>(x, gamma, beta, out);
}